// round 14
// baseline (speedup 1.0000x reference)
#include <cuda_runtime.h>
#include <cuda_bf16.h>
#include <cstdint>
#include <cstddef>

// Problem dims
#define TT 512
#define BB 64
#define DD 1024
#define HH 1024
#define FOURH 4096
#define TBH (TT * BB * HH)   // 33554432
#define BH  (BB * HH)        // 65536

// Persistent-kernel config
#define NCTA 128          // <= 148 SMs, 1 CTA/SM -> co-resident
#define NTHR 256

// ---------------- scratch ------------------------------------------------------
__device__ float g_gx[(size_t)TT * FOURH * BB];   // 512 MB: Gx[t][j][b]
__device__ float g_h[2][BH];                      // h double buffer
__device__ unsigned int g_bar[TT];                // per-step grid barrier counters

// ---------------- Phase 1: Gx[t][j][b] = bias[j] + sum_d X[t,b,d]*W_ih[j,d] ---
// SGEMM M = T*B = 32768, N = 4096, K = 1024. Double-buffered smem, reg prefetch,
// 2 CTAs/SM. Also zeroes the phase-2 grid-barrier counters (block 0).
#define BM 128
#define BN 128
#define BKK 16

__global__ __launch_bounds__(256, 2)
void gemm_xwih_kernel(const float* __restrict__ X,
                      const float* __restrict__ W,     // W_ih [4096][1024]
                      const float* __restrict__ b_ih,
                      const float* __restrict__ b_hh) {
    __shared__ float As[2][BKK][BM];
    __shared__ float Bs[2][BKK][BN];

    const int tid = threadIdx.x;

    // reset phase-2 barrier counters (done by one block; gemm completes before lstm)
    if (blockIdx.x == 0 && blockIdx.y == 0) {
        g_bar[tid] = 0u;
        g_bar[tid + 256] = 0u;
    }

    const int m0 = blockIdx.y * BM;
    const int n0 = blockIdx.x * BN;
    const int tm = (tid >> 4) * 8;   // m micro-offset
    const int tn = (tid & 15) * 8;   // n micro-offset

    // loader mapping: idx = tid + r*256 -> (m = idx>>2, kq = (idx&3)*4)
    const int lm0 = tid >> 2;
    const int lkq = (tid & 3) * 4;

    float4 pa[2], pb[2];

    // prologue: load tile 0 into regs, store to buffer 0
    {
        const float* Xp = X + (size_t)(m0 + lm0) * DD + lkq;
        const float* Wp = W + (size_t)(n0 + lm0) * DD + lkq;
        pa[0] = *(const float4*)Xp;            pb[0] = *(const float4*)Wp;
        pa[1] = *(const float4*)(Xp + 64 * DD); pb[1] = *(const float4*)(Wp + 64 * DD);
    }
#pragma unroll
    for (int r = 0; r < 2; r++) {
        int m = lm0 + 64 * r;
        As[0][lkq + 0][m] = pa[r].x; As[0][lkq + 1][m] = pa[r].y;
        As[0][lkq + 2][m] = pa[r].z; As[0][lkq + 3][m] = pa[r].w;
        Bs[0][lkq + 0][m] = pb[r].x; Bs[0][lkq + 1][m] = pb[r].y;
        Bs[0][lkq + 2][m] = pb[r].z; Bs[0][lkq + 3][m] = pb[r].w;
    }
    __syncthreads();

    float acc[8][8];
#pragma unroll
    for (int i = 0; i < 8; i++)
#pragma unroll
        for (int j = 0; j < 8; j++) acc[i][j] = 0.f;

    const int NKT = DD / BKK;   // 64
    for (int kt = 0; kt < NKT; kt++) {
        const int buf = kt & 1;

        // prefetch next tile into registers (latency hides under compute)
        if (kt < NKT - 1) {
            int k0 = (kt + 1) * BKK;
            const float* Xp = X + (size_t)(m0 + lm0) * DD + k0 + lkq;
            const float* Wp = W + (size_t)(n0 + lm0) * DD + k0 + lkq;
            pa[0] = *(const float4*)Xp;            pb[0] = *(const float4*)Wp;
            pa[1] = *(const float4*)(Xp + 64 * DD); pb[1] = *(const float4*)(Wp + 64 * DD);
        }

#pragma unroll
        for (int k = 0; k < BKK; k++) {
            float4 a0 = *(const float4*)&As[buf][k][tm];
            float4 a1 = *(const float4*)&As[buf][k][tm + 4];
            float4 c0 = *(const float4*)&Bs[buf][k][tn];
            float4 c1 = *(const float4*)&Bs[buf][k][tn + 4];
            float av[8] = {a0.x, a0.y, a0.z, a0.w, a1.x, a1.y, a1.z, a1.w};
            float bv[8] = {c0.x, c0.y, c0.z, c0.w, c1.x, c1.y, c1.z, c1.w};
#pragma unroll
            for (int i = 0; i < 8; i++)
#pragma unroll
                for (int j = 0; j < 8; j++)
                    acc[i][j] += av[i] * bv[j];
        }

        if (kt < NKT - 1) {
            const int nb = buf ^ 1;   // safe: all warps finished reading nb last iter
#pragma unroll
            for (int r = 0; r < 2; r++) {
                int m = lm0 + 64 * r;
                As[nb][lkq + 0][m] = pa[r].x; As[nb][lkq + 1][m] = pa[r].y;
                As[nb][lkq + 2][m] = pa[r].z; As[nb][lkq + 3][m] = pa[r].w;
                Bs[nb][lkq + 0][m] = pb[r].x; Bs[nb][lkq + 1][m] = pb[r].y;
                Bs[nb][lkq + 2][m] = pb[r].z; Bs[nb][lkq + 3][m] = pb[r].w;
            }
            __syncthreads();
        }
    }

    // Epilogue: Gx[t][j][b], b-contiguous stores
    const int m = m0 + tm;
    const int t = m >> 6;
    const int b = m & 63;
#pragma unroll
    for (int j = 0; j < 8; j++) {
        int jg = n0 + tn + j;
        float bias = b_ih[jg] + b_hh[jg];
        float* dst = g_gx + ((size_t)t * FOURH + jg) * BB + b;
        float4 v0 = make_float4(acc[0][j] + bias, acc[1][j] + bias,
                                acc[2][j] + bias, acc[3][j] + bias);
        float4 v1 = make_float4(acc[4][j] + bias, acc[5][j] + bias,
                                acc[6][j] + bias, acc[7][j] + bias);
        *(float4*)dst       = v0;
        *(float4*)(dst + 4) = v1;
    }
}

// ---------------- Phase 2: persistent sequential LSTM --------------------------
// CTA ct owns hidden columns ct*8..ct*8+7 and all 4 gates (32 W_hh rows = 128 KB
// cached in smem for all 512 steps). Warp w = (gate jg = w&3, b-half bh = w>>2);
// each thread: 8 gate-columns x 1 batch row -> h smem traffic 0.63 B/FMA (FMA-bound).
#define HS_STRIDE 132          // conflict-free AND 16B-aligned rows
#define HSBUF (64 * HS_STRIDE)
#define GS_STRIDE 65
#define SMEM_P2 ((32 * HH + 2 * HSBUF + 32 * GS_STRIDE) * 4)   // 206976 bytes

__device__ __forceinline__ float sigmoidf_(float x) {
    return 1.0f / (1.0f + __expf(-x));
}

__global__ __launch_bounds__(NTHR, 1)
void lstm_seq_kernel(const float* __restrict__ h0,
                     const float* __restrict__ c0,
                     const float* __restrict__ Whh,   // [4096][1024]
                     float* __restrict__ out) {
    extern __shared__ float sm[];
    float* Wsh = sm;                         // [32][1024]
    float* hsA = sm + 32 * HH;               // [64][132] double buffer
    float* hsB = hsA + HSBUF;
    float* gsh = hsB + HSBUF;                // [32][65]

    const int tid  = threadIdx.x;
    const int ct   = blockIdx.x;             // 0..127
    const int lane = tid & 31;
    const int w    = tid >> 5;               // warp 0..7
    const int jg   = w & 3;                  // gate 0..3
    const int bh   = w >> 2;                 // b-half 0..1
    const int b    = bh * 32 + lane;         // this thread's batch row

    // ---- load W_hh slice into shared (once): row j = gate*8+nl ----
    {
        const float4* Wv = (const float4*)Whh;
        float4* Ws4 = (float4*)Wsh;
        for (int idx = tid; idx < 32 * 256; idx += NTHR) {
            int row  = idx >> 8;
            int col  = idx & 255;
            int gate = row >> 3, nl = row & 7;
            size_t jgl = (size_t)gate * 1024 + ct * 8 + nl;
            Ws4[row * 256 + col] = Wv[jgl * 256 + col];
        }
    }

    // ---- cell state: thread owns (b_e = tid>>2, nl = (tid&3)*2 + {0,1}) ----
    const int be  = tid >> 2;
    const int nl0 = (tid & 3) * 2;
    float c_reg[2];
    c_reg[0] = c0[be * HH + ct * 8 + nl0];
    c_reg[1] = c0[be * HH + ct * 8 + nl0 + 1];
    __syncthreads();

    // W row base for this warp's gate (float4 units)
    const float4* wbase = (const float4*)Wsh + (jg * 8) * 256;

    for (int t = 0; t < TT; t++) {
        const float* hsrc = (t == 0) ? h0 : g_h[t & 1];

        // prologue: load chunk 0 (warp w loads rows w, w+8, ..., w+56)
        float4 v[8];
#pragma unroll
        for (int i = 0; i < 8; i++)
            v[i] = __ldcg((const float4*)(hsrc + (size_t)(w + 8 * i) * HH) + lane);
#pragma unroll
        for (int i = 0; i < 8; i++)
            *(float4*)(hsA + (w + 8 * i) * HS_STRIDE + 4 * lane) = v[i];
        __syncthreads();

        float acc[8];
#pragma unroll
        for (int jj = 0; jj < 8; jj++) acc[jj] = 0.f;

        for (int c = 0; c < 8; c++) {
            // prefetch next chunk into regs (overlaps with compute below)
            if (c < 7) {
                int kc = (c + 1) * 128;
#pragma unroll
                for (int i = 0; i < 8; i++)
                    v[i] = __ldcg((const float4*)(hsrc + (size_t)(w + 8 * i) * HH + kc) + lane);
            }

            const float* cur = (c & 1) ? hsB : hsA;
            const float*  hp = cur + b * HS_STRIDE;
            const float4* wb = wbase + ((c * 128) >> 2);
#pragma unroll 4
            for (int k4 = 0; k4 < 32; k4++) {
                float4 hv = *(const float4*)(hp + 4 * k4);
#pragma unroll
                for (int jj = 0; jj < 8; jj++) {
                    float4 wv = wb[jj * 256 + k4];
                    acc[jj] = fmaf(wv.x, hv.x, acc[jj]);
                    acc[jj] = fmaf(wv.y, hv.y, acc[jj]);
                    acc[jj] = fmaf(wv.z, hv.z, acc[jj]);
                    acc[jj] = fmaf(wv.w, hv.w, acc[jj]);
                }
            }

            if (c < 7) {
                __syncthreads();   // everyone done with the buffer we overwrite
                float* nxt = (c & 1) ? hsA : hsB;
#pragma unroll
                for (int i = 0; i < 8; i++)
                    *(float4*)(nxt + (w + 8 * i) * HS_STRIDE + 4 * lane) = v[i];
                __syncthreads();
            }
        }

        // add precomputed input projection: jglob = jg*1024 + ct*8 + jj
        {
            const float* gp = g_gx + ((size_t)t * FOURH + jg * 1024 + ct * 8) * BB + b;
#pragma unroll
            for (int jj = 0; jj < 8; jj++)
                acc[jj] += __ldcs(gp + jj * BB);
        }

        // exchange gates through smem: gsh[(jg*8+jj)*65 + b]
        __syncthreads();
#pragma unroll
        for (int jj = 0; jj < 8; jj++)
            gsh[(jg * 8 + jj) * GS_STRIDE + b] = acc[jj];
        __syncthreads();

        // elementwise cell update: 2 consecutive nl per thread -> float2 stores
        float* hdst = g_h[(t + 1) & 1];
        float hv2[2], cv2[2];
#pragma unroll
        for (int r = 0; r < 2; r++) {
            int nl = nl0 + r;
            float ig = gsh[(0  + nl) * GS_STRIDE + be];
            float fg = gsh[(8  + nl) * GS_STRIDE + be];
            float gg = gsh[(16 + nl) * GS_STRIDE + be];
            float og = gsh[(24 + nl) * GS_STRIDE + be];
            float iv = sigmoidf_(ig);
            float fv = sigmoidf_(fg);
            float gv = tanhf(gg);
            float ov = sigmoidf_(og);
            float cv = fv * c_reg[r] + iv * gv;
            float hv = ov * tanhf(cv);
            c_reg[r] = cv;
            hv2[r] = hv; cv2[r] = cv;
        }
        {
            size_t off = (size_t)be * HH + ct * 8 + nl0;
            float2 hvv = make_float2(hv2[0], hv2[1]);
            *(float2*)(out + (size_t)t * BH + off) = hvv;
            __stcg((float2*)(hdst + off), hvv);
            if (t == TT - 1) {
                *(float2*)(out + (size_t)TBH + off)      = hvv;                       // h_T
                *(float2*)(out + (size_t)TBH + BH + off) = make_float2(cv2[0], cv2[1]); // c_T
            }
        }

        // ---- grid barrier ----
        __threadfence();
        __syncthreads();
        if (tid == 0) {
            atomicAdd(&g_bar[t], 1u);
            while (*((volatile unsigned int*)&g_bar[t]) < (unsigned)NCTA) { }
            __threadfence();
        }
        __syncthreads();
    }
}

// ---------------- launch --------------------------------------------------------
extern "C" void kernel_launch(void* const* d_in, const int* in_sizes, int n_in,
                              void* d_out, int out_size) {
    const float* X    = (const float*)d_in[0];   // [T,B,D]
    const float* h0   = (const float*)d_in[1];   // [B,H]
    const float* c0   = (const float*)d_in[2];   // [B,H]
    const float* Wih  = (const float*)d_in[3];   // [4H,D]
    const float* Whh  = (const float*)d_in[4];   // [4H,H]
    const float* b_ih = (const float*)d_in[5];   // [4H]
    const float* b_hh = (const float*)d_in[6];   // [4H]
    float* out = (float*)d_out;

    cudaFuncSetAttribute(lstm_seq_kernel,
                         cudaFuncAttributeMaxDynamicSharedMemorySize, SMEM_P2);

    dim3 g1(FOURH / BN, (TT * BB) / BM);   // (32, 256)
    gemm_xwih_kernel<<<g1, 256>>>(X, Wih, b_ih, b_hh);

    lstm_seq_kernel<<<NCTA, NTHR, SMEM_P2>>>(h0, c0, Whh, out);
}

// round 15
// speedup vs baseline: 1.0011x; 1.0011x over previous
#include <cuda_runtime.h>
#include <cuda_bf16.h>
#include <cstdint>
#include <cstddef>

// Problem dims
#define TT 512
#define BB 64
#define DD 1024
#define HH 1024
#define FOURH 4096
#define TBH (TT * BB * HH)   // 33554432
#define BH  (BB * HH)        // 65536

// Persistent-kernel config
#define NCTA 128          // <= 148 SMs, 1 CTA/SM -> co-resident
#define NTHR 256

// ---------------- scratch ------------------------------------------------------
__device__ float g_gx[(size_t)TT * FOURH * BB];   // 512 MB: Gx[t][j][b]
__device__ float g_h[2][BH];                      // h double buffer
__device__ unsigned int g_bar[TT];                // per-step grid barrier counters

// ---------------- Phase 1: Gx[t][j][b] = bias[j] + sum_d X[t,b,d]*W_ih[j,d] ---
// SGEMM M = T*B = 32768, N = 4096, K = 1024. Double-buffered smem, reg prefetch,
// 2 CTAs/SM. Also zeroes the phase-2 grid-barrier counters (block 0).
#define BM 128
#define BN 128
#define BKK 16

__global__ __launch_bounds__(256, 2)
void gemm_xwih_kernel(const float* __restrict__ X,
                      const float* __restrict__ W,     // W_ih [4096][1024]
                      const float* __restrict__ b_ih,
                      const float* __restrict__ b_hh) {
    __shared__ float As[2][BKK][BM];
    __shared__ float Bs[2][BKK][BN];

    const int tid = threadIdx.x;

    // reset phase-2 barrier counters (done by one block; gemm completes before lstm)
    if (blockIdx.x == 0 && blockIdx.y == 0) {
        g_bar[tid] = 0u;
        g_bar[tid + 256] = 0u;
    }

    const int m0 = blockIdx.y * BM;
    const int n0 = blockIdx.x * BN;
    const int tm = (tid >> 4) * 8;   // m micro-offset
    const int tn = (tid & 15) * 8;   // n micro-offset

    // loader mapping: idx = tid + r*256 -> (m = idx>>2, kq = (idx&3)*4)
    const int lm0 = tid >> 2;
    const int lkq = (tid & 3) * 4;

    float4 pa[2], pb[2];

    // prologue: load tile 0 into regs, store to buffer 0
    {
        const float* Xp = X + (size_t)(m0 + lm0) * DD + lkq;
        const float* Wp = W + (size_t)(n0 + lm0) * DD + lkq;
        pa[0] = *(const float4*)Xp;            pb[0] = *(const float4*)Wp;
        pa[1] = *(const float4*)(Xp + 64 * DD); pb[1] = *(const float4*)(Wp + 64 * DD);
    }
#pragma unroll
    for (int r = 0; r < 2; r++) {
        int m = lm0 + 64 * r;
        As[0][lkq + 0][m] = pa[r].x; As[0][lkq + 1][m] = pa[r].y;
        As[0][lkq + 2][m] = pa[r].z; As[0][lkq + 3][m] = pa[r].w;
        Bs[0][lkq + 0][m] = pb[r].x; Bs[0][lkq + 1][m] = pb[r].y;
        Bs[0][lkq + 2][m] = pb[r].z; Bs[0][lkq + 3][m] = pb[r].w;
    }
    __syncthreads();

    float acc[8][8];
#pragma unroll
    for (int i = 0; i < 8; i++)
#pragma unroll
        for (int j = 0; j < 8; j++) acc[i][j] = 0.f;

    const int NKT = DD / BKK;   // 64
    for (int kt = 0; kt < NKT; kt++) {
        const int buf = kt & 1;

        // prefetch next tile into registers (latency hides under compute)
        if (kt < NKT - 1) {
            int k0 = (kt + 1) * BKK;
            const float* Xp = X + (size_t)(m0 + lm0) * DD + k0 + lkq;
            const float* Wp = W + (size_t)(n0 + lm0) * DD + k0 + lkq;
            pa[0] = *(const float4*)Xp;            pb[0] = *(const float4*)Wp;
            pa[1] = *(const float4*)(Xp + 64 * DD); pb[1] = *(const float4*)(Wp + 64 * DD);
        }

#pragma unroll
        for (int k = 0; k < BKK; k++) {
            float4 a0 = *(const float4*)&As[buf][k][tm];
            float4 a1 = *(const float4*)&As[buf][k][tm + 4];
            float4 c0 = *(const float4*)&Bs[buf][k][tn];
            float4 c1 = *(const float4*)&Bs[buf][k][tn + 4];
            float av[8] = {a0.x, a0.y, a0.z, a0.w, a1.x, a1.y, a1.z, a1.w};
            float bv[8] = {c0.x, c0.y, c0.z, c0.w, c1.x, c1.y, c1.z, c1.w};
#pragma unroll
            for (int i = 0; i < 8; i++)
#pragma unroll
                for (int j = 0; j < 8; j++)
                    acc[i][j] += av[i] * bv[j];
        }

        if (kt < NKT - 1) {
            const int nb = buf ^ 1;   // safe: all warps finished reading nb last iter
#pragma unroll
            for (int r = 0; r < 2; r++) {
                int m = lm0 + 64 * r;
                As[nb][lkq + 0][m] = pa[r].x; As[nb][lkq + 1][m] = pa[r].y;
                As[nb][lkq + 2][m] = pa[r].z; As[nb][lkq + 3][m] = pa[r].w;
                Bs[nb][lkq + 0][m] = pb[r].x; Bs[nb][lkq + 1][m] = pb[r].y;
                Bs[nb][lkq + 2][m] = pb[r].z; Bs[nb][lkq + 3][m] = pb[r].w;
            }
            __syncthreads();
        }
    }

    // Epilogue: Gx[t][j][b], b-contiguous stores
    const int m = m0 + tm;
    const int t = m >> 6;
    const int b = m & 63;
#pragma unroll
    for (int j = 0; j < 8; j++) {
        int jg = n0 + tn + j;
        float bias = b_ih[jg] + b_hh[jg];
        float* dst = g_gx + ((size_t)t * FOURH + jg) * BB + b;
        float4 v0 = make_float4(acc[0][j] + bias, acc[1][j] + bias,
                                acc[2][j] + bias, acc[3][j] + bias);
        float4 v1 = make_float4(acc[4][j] + bias, acc[5][j] + bias,
                                acc[6][j] + bias, acc[7][j] + bias);
        *(float4*)dst       = v0;
        *(float4*)(dst + 4) = v1;
    }
}

// ---------------- Phase 2: persistent sequential LSTM --------------------------
// CTA ct owns hidden columns ct*8..ct*8+7 and all 4 gates (32 W_hh rows = 128 KB
// cached in smem for all 512 steps). Warp w = (gate jg = w&3, b-half bh = w>>2);
// each thread: 8 gate-columns x 1 batch row -> h smem traffic 0.63 B/FMA (FMA-bound).
#define HS_STRIDE 132          // conflict-free AND 16B-aligned rows
#define HSBUF (64 * HS_STRIDE)
#define GS_STRIDE 65
#define SMEM_P2 ((32 * HH + 2 * HSBUF + 32 * GS_STRIDE) * 4)   // 206976 bytes

__device__ __forceinline__ float sigmoidf_(float x) {
    return 1.0f / (1.0f + __expf(-x));
}

__global__ __launch_bounds__(NTHR, 1)
void lstm_seq_kernel(const float* __restrict__ h0,
                     const float* __restrict__ c0,
                     const float* __restrict__ Whh,   // [4096][1024]
                     float* __restrict__ out) {
    extern __shared__ float sm[];
    float* Wsh = sm;                         // [32][1024]
    float* hsA = sm + 32 * HH;               // [64][132] double buffer
    float* hsB = hsA + HSBUF;
    float* gsh = hsB + HSBUF;                // [32][65]

    const int tid  = threadIdx.x;
    const int ct   = blockIdx.x;             // 0..127
    const int lane = tid & 31;
    const int w    = tid >> 5;               // warp 0..7
    const int jg   = w & 3;                  // gate 0..3
    const int bh   = w >> 2;                 // b-half 0..1
    const int b    = bh * 32 + lane;         // this thread's batch row

    // ---- load W_hh slice into shared (once): row j = gate*8+nl ----
    {
        const float4* Wv = (const float4*)Whh;
        float4* Ws4 = (float4*)Wsh;
        for (int idx = tid; idx < 32 * 256; idx += NTHR) {
            int row  = idx >> 8;
            int col  = idx & 255;
            int gate = row >> 3, nl = row & 7;
            size_t jgl = (size_t)gate * 1024 + ct * 8 + nl;
            Ws4[row * 256 + col] = Wv[jgl * 256 + col];
        }
    }

    // ---- cell state: thread owns (b_e = tid>>2, nl = (tid&3)*2 + {0,1}) ----
    const int be  = tid >> 2;
    const int nl0 = (tid & 3) * 2;
    float c_reg[2];
    c_reg[0] = c0[be * HH + ct * 8 + nl0];
    c_reg[1] = c0[be * HH + ct * 8 + nl0 + 1];
    __syncthreads();

    // W row base for this warp's gate (float4 units)
    const float4* wbase = (const float4*)Wsh + (jg * 8) * 256;

    for (int t = 0; t < TT; t++) {
        const float* hsrc = (t == 0) ? h0 : g_h[t & 1];

        // prologue: load chunk 0 (warp w loads rows w, w+8, ..., w+56)
        float4 v[8];
#pragma unroll
        for (int i = 0; i < 8; i++)
            v[i] = __ldcg((const float4*)(hsrc + (size_t)(w + 8 * i) * HH) + lane);
#pragma unroll
        for (int i = 0; i < 8; i++)
            *(float4*)(hsA + (w + 8 * i) * HS_STRIDE + 4 * lane) = v[i];
        __syncthreads();

        float acc[8];
#pragma unroll
        for (int jj = 0; jj < 8; jj++) acc[jj] = 0.f;

        for (int c = 0; c < 8; c++) {
            // prefetch next chunk into regs (overlaps with compute below)
            if (c < 7) {
                int kc = (c + 1) * 128;
#pragma unroll
                for (int i = 0; i < 8; i++)
                    v[i] = __ldcg((const float4*)(hsrc + (size_t)(w + 8 * i) * HH + kc) + lane);
            }

            const float* cur = (c & 1) ? hsB : hsA;
            const float*  hp = cur + b * HS_STRIDE;
            const float4* wb = wbase + ((c * 128) >> 2);
#pragma unroll 4
            for (int k4 = 0; k4 < 32; k4++) {
                float4 hv = *(const float4*)(hp + 4 * k4);
#pragma unroll
                for (int jj = 0; jj < 8; jj++) {
                    float4 wv = wb[jj * 256 + k4];
                    acc[jj] = fmaf(wv.x, hv.x, acc[jj]);
                    acc[jj] = fmaf(wv.y, hv.y, acc[jj]);
                    acc[jj] = fmaf(wv.z, hv.z, acc[jj]);
                    acc[jj] = fmaf(wv.w, hv.w, acc[jj]);
                }
            }

            if (c < 7) {
                __syncthreads();   // everyone done with the buffer we overwrite
                float* nxt = (c & 1) ? hsA : hsB;
#pragma unroll
                for (int i = 0; i < 8; i++)
                    *(float4*)(nxt + (w + 8 * i) * HS_STRIDE + 4 * lane) = v[i];
                __syncthreads();
            }
        }

        // add precomputed input projection: jglob = jg*1024 + ct*8 + jj
        {
            const float* gp = g_gx + ((size_t)t * FOURH + jg * 1024 + ct * 8) * BB + b;
#pragma unroll
            for (int jj = 0; jj < 8; jj++)
                acc[jj] += __ldcs(gp + jj * BB);
        }

        // exchange gates through smem: gsh[(jg*8+jj)*65 + b]
        __syncthreads();
#pragma unroll
        for (int jj = 0; jj < 8; jj++)
            gsh[(jg * 8 + jj) * GS_STRIDE + b] = acc[jj];
        __syncthreads();

        // elementwise cell update: 2 consecutive nl per thread -> float2 stores
        float* hdst = g_h[(t + 1) & 1];
        float hv2[2], cv2[2];
#pragma unroll
        for (int r = 0; r < 2; r++) {
            int nl = nl0 + r;
            float ig = gsh[(0  + nl) * GS_STRIDE + be];
            float fg = gsh[(8  + nl) * GS_STRIDE + be];
            float gg = gsh[(16 + nl) * GS_STRIDE + be];
            float og = gsh[(24 + nl) * GS_STRIDE + be];
            float iv = sigmoidf_(ig);
            float fv = sigmoidf_(fg);
            float gv = tanhf(gg);
            float ov = sigmoidf_(og);
            float cv = fv * c_reg[r] + iv * gv;
            float hv = ov * tanhf(cv);
            c_reg[r] = cv;
            hv2[r] = hv; cv2[r] = cv;
        }
        {
            size_t off = (size_t)be * HH + ct * 8 + nl0;
            float2 hvv = make_float2(hv2[0], hv2[1]);
            *(float2*)(out + (size_t)t * BH + off) = hvv;
            __stcg((float2*)(hdst + off), hvv);
            if (t == TT - 1) {
                *(float2*)(out + (size_t)TBH + off)      = hvv;                       // h_T
                *(float2*)(out + (size_t)TBH + BH + off) = make_float2(cv2[0], cv2[1]); // c_T
            }
        }

        // ---- grid barrier ----
        __threadfence();
        __syncthreads();
        if (tid == 0) {
            atomicAdd(&g_bar[t], 1u);
            while (*((volatile unsigned int*)&g_bar[t]) < (unsigned)NCTA) { }
            __threadfence();
        }
        __syncthreads();
    }
}

// ---------------- launch --------------------------------------------------------
extern "C" void kernel_launch(void* const* d_in, const int* in_sizes, int n_in,
                              void* d_out, int out_size) {
    const float* X    = (const float*)d_in[0];   // [T,B,D]
    const float* h0   = (const float*)d_in[1];   // [B,H]
    const float* c0   = (const float*)d_in[2];   // [B,H]
    const float* Wih  = (const float*)d_in[3];   // [4H,D]
    const float* Whh  = (const float*)d_in[4];   // [4H,H]
    const float* b_ih = (const float*)d_in[5];   // [4H]
    const float* b_hh = (const float*)d_in[6];   // [4H]
    float* out = (float*)d_out;

    cudaFuncSetAttribute(lstm_seq_kernel,
                         cudaFuncAttributeMaxDynamicSharedMemorySize, SMEM_P2);

    dim3 g1(FOURH / BN, (TT * BB) / BM);   // (32, 256)
    gemm_xwih_kernel<<<g1, 256>>>(X, Wih, b_ih, b_hh);

    lstm_seq_kernel<<<NCTA, NTHR, SMEM_P2>>>(h0, c0, Whh, out);
}

// round 16
// speedup vs baseline: 1.1614x; 1.1601x over previous
#include <cuda_runtime.h>
#include <cuda_bf16.h>
#include <cstdint>
#include <cstddef>

// Problem dims
#define TT 512
#define BB 64
#define DD 1024
#define HH 1024
#define FOURH 4096
#define TBH (TT * BB * HH)   // 33554432
#define BH  (BB * HH)        // 65536

// Persistent-kernel config
#define NCTA 128
#define NTHR 256

// ---------------- scratch ------------------------------------------------------
__device__ float g_gx[(size_t)TT * FOURH * BB];        // 512 MB: Gx[t][j][b]
__device__ float g_h[2][BH];                           // h double buffer
__device__ unsigned int g_bar[TT];                     // per-step barrier counters
__device__ __nv_bfloat16 g_xhi[(size_t)TT * BB * DD];  // 64 MB
__device__ __nv_bfloat16 g_xlo[(size_t)TT * BB * DD];  // 64 MB
__device__ __nv_bfloat16 g_whi[(size_t)FOURH * DD];    // 8 MB
__device__ __nv_bfloat16 g_wlo[(size_t)FOURH * DD];    // 8 MB

// ---------------- Phase 0: split fp32 -> bf16 hi/lo; zero barriers --------------
#define NX4 ((size_t)TT * BB * DD / 4)     // 8388608 float4 units
#define NW4 ((size_t)FOURH * DD / 4)       // 1048576

__device__ __forceinline__ void split4(float4 v, __nv_bfloat162* hp, __nv_bfloat162* lp) {
    __nv_bfloat16 hx = __float2bfloat16_rn(v.x);
    __nv_bfloat16 hy = __float2bfloat16_rn(v.y);
    __nv_bfloat16 hz = __float2bfloat16_rn(v.z);
    __nv_bfloat16 hw = __float2bfloat16_rn(v.w);
    __nv_bfloat16 lx = __float2bfloat16_rn(v.x - __bfloat162float(hx));
    __nv_bfloat16 ly = __float2bfloat16_rn(v.y - __bfloat162float(hy));
    __nv_bfloat16 lz = __float2bfloat16_rn(v.z - __bfloat162float(hz));
    __nv_bfloat16 lw = __float2bfloat16_rn(v.w - __bfloat162float(hw));
    hp[0] = __halves2bfloat162(hx, hy);
    hp[1] = __halves2bfloat162(hz, hw);
    lp[0] = __halves2bfloat162(lx, ly);
    lp[1] = __halves2bfloat162(lz, lw);
}

__global__ __launch_bounds__(256)
void convert_split_kernel(const float* __restrict__ X, const float* __restrict__ W) {
    if (blockIdx.x == 0) {
        for (int i = threadIdx.x; i < TT; i += blockDim.x) g_bar[i] = 0u;
    }
    size_t stride = (size_t)gridDim.x * blockDim.x;
    size_t total = NX4 + NW4;
    for (size_t i = (size_t)blockIdx.x * blockDim.x + threadIdx.x; i < total; i += stride) {
        if (i < NX4) {
            float4 v = ((const float4*)X)[i];
            split4(v, (__nv_bfloat162*)g_xhi + i * 2, (__nv_bfloat162*)g_xlo + i * 2);
        } else {
            size_t j = i - NX4;
            float4 v = ((const float4*)W)[j];
            split4(v, (__nv_bfloat162*)g_whi + j * 2, (__nv_bfloat162*)g_wlo + j * 2);
        }
    }
}

// ---------------- Phase 1: bf16-split tensor-core GEMM --------------------------
// Gx[t][j][b] = bias[j] + sum_d X[m,d]*W[j,d],  m = t*64+b.
// C = Xhi*Whi' + Xhi*Wlo' + Xlo*Whi'  (fp32 accum) via mma.sync m16n8k16.
// CTA tile 128x128, 8 warps as 2(m) x 4(n), warp tile 64x32.
#define ASTRIDE 40              // bf16 elems per smem row (128B pad-free-ish)
#define ABYTES (128 * ASTRIDE * 2)
#define CSTRIDE 33
#define SMEM_G (2 * ABYTES * 2 + 128 * CSTRIDE * 4)   // A(2buf)+B(2buf)+C = 57856

__device__ __forceinline__ uint32_t smem_u32(const void* p) {
    return (uint32_t)__cvta_generic_to_shared(p);
}

__device__ __forceinline__ void ldsm4(uint32_t* r, uint32_t addr) {
    asm volatile("ldmatrix.sync.aligned.m8n8.x4.shared.b16 {%0,%1,%2,%3}, [%4];\n"
                 : "=r"(r[0]), "=r"(r[1]), "=r"(r[2]), "=r"(r[3]) : "r"(addr));
}

__device__ __forceinline__ void mma16816(float* c, const uint32_t* a, uint32_t b0, uint32_t b1) {
    asm volatile(
        "mma.sync.aligned.m16n8k16.row.col.f32.bf16.bf16.f32 "
        "{%0,%1,%2,%3}, {%4,%5,%6,%7}, {%8,%9}, {%0,%1,%2,%3};\n"
        : "+f"(c[0]), "+f"(c[1]), "+f"(c[2]), "+f"(c[3])
        : "r"(a[0]), "r"(a[1]), "r"(a[2]), "r"(a[3]), "r"(b0), "r"(b1));
}

__global__ __launch_bounds__(256)
void gemm_xwih_mma(const float* __restrict__ b_ih, const float* __restrict__ b_hh) {
    extern __shared__ char smg[];
    __nv_bfloat16* As = (__nv_bfloat16*)smg;                    // [2][128*ASTRIDE]
    __nv_bfloat16* Bs = (__nv_bfloat16*)(smg + 2 * ABYTES);     // [2][128*ASTRIDE]
    float*         Cs = (float*)(smg + 4 * ABYTES);             // [128*CSTRIDE]

    const int tid  = threadIdx.x;
    const int lane = tid & 31;
    const int wid  = tid >> 5;
    const int warp_m = wid >> 2;      // 0..1
    const int warp_n = wid & 3;       // 0..3
    const int m0 = blockIdx.y * 128;
    const int n0 = blockIdx.x * 128;

    // loader mapping: idx = tid + i*256 -> row = idx>>2, kseg = (idx&3)*8
    const int lr = tid >> 2;          // 0..63 (+64 for i=1)
    const int lk = (tid & 3) * 8;

    const __nv_bfloat16* Aseg[3] = {g_xhi, g_xhi, g_xlo};
    const __nv_bfloat16* Bseg[3] = {g_whi, g_wlo, g_whi};

    float acc[4][4][4];
#pragma unroll
    for (int mi = 0; mi < 4; mi++)
#pragma unroll
        for (int ni = 0; ni < 4; ni++)
#pragma unroll
            for (int r = 0; r < 4; r++) acc[mi][ni][r] = 0.f;

    float4 pa[2], pb[2];
    // prologue: it = 0 (seg 0, kc 0)
    {
        const __nv_bfloat16* Ap = Aseg[0] + (size_t)(m0 + lr) * DD + lk;
        const __nv_bfloat16* Bp = Bseg[0] + (size_t)(n0 + lr) * DD + lk;
        pa[0] = *(const float4*)Ap;  pa[1] = *(const float4*)(Ap + (size_t)64 * DD);
        pb[0] = *(const float4*)Bp;  pb[1] = *(const float4*)(Bp + (size_t)64 * DD);
    }
#pragma unroll
    for (int r = 0; r < 2; r++) {
        *(float4*)(As + (lr + 64 * r) * ASTRIDE + lk) = pa[r];
        *(float4*)(Bs + (lr + 64 * r) * ASTRIDE + lk) = pb[r];
    }
    __syncthreads();

    const int NIT = 96;    // 3 segments x 32 chunks of k32
    for (int it = 0; it < NIT; it++) {
        const int buf = it & 1;
        __nv_bfloat16* Ab = As + buf * (128 * ASTRIDE);
        __nv_bfloat16* Bb = Bs + buf * (128 * ASTRIDE);

        if (it < NIT - 1) {
            int nit = it + 1;
            int seg = nit >> 5;
            int kc  = (nit & 31) * 32;
            const __nv_bfloat16* Ap = Aseg[seg] + (size_t)(m0 + lr) * DD + kc + lk;
            const __nv_bfloat16* Bp = Bseg[seg] + (size_t)(n0 + lr) * DD + kc + lk;
            pa[0] = *(const float4*)Ap;  pa[1] = *(const float4*)(Ap + (size_t)64 * DD);
            pb[0] = *(const float4*)Bp;  pb[1] = *(const float4*)(Bp + (size_t)64 * DD);
        }

#pragma unroll
        for (int kk = 0; kk < 32; kk += 16) {
            uint32_t af[4][4];
#pragma unroll
            for (int mi = 0; mi < 4; mi++) {
                uint32_t addr = smem_u32(Ab + (warp_m * 64 + mi * 16 + (lane & 15)) * ASTRIDE
                                            + kk + (lane >> 4) * 8);
                ldsm4(af[mi], addr);
            }
            uint32_t bf[2][4];
#pragma unroll
            for (int bi = 0; bi < 2; bi++) {
                uint32_t addr = smem_u32(Bb + (warp_n * 32 + bi * 16 + (lane & 15)) * ASTRIDE
                                            + kk + (lane >> 4) * 8);
                ldsm4(bf[bi], addr);
            }
#pragma unroll
            for (int mi = 0; mi < 4; mi++)
#pragma unroll
                for (int ni = 0; ni < 4; ni++) {
                    int bi = ni >> 1, sub = ni & 1;
                    mma16816(acc[mi][ni], af[mi], bf[bi][sub], bf[bi][sub + 2]);
                }
        }

        if (it < NIT - 1) {
            __nv_bfloat16* An = As + (buf ^ 1) * (128 * ASTRIDE);
            __nv_bfloat16* Bn = Bs + (buf ^ 1) * (128 * ASTRIDE);
#pragma unroll
            for (int r = 0; r < 2; r++) {
                *(float4*)(An + (lr + 64 * r) * ASTRIDE + lk) = pa[r];
                *(float4*)(Bn + (lr + 64 * r) * ASTRIDE + lk) = pb[r];
            }
            __syncthreads();
        }
    }

    // Epilogue: stage each 128x32 n-block through smem -> b-contiguous g_gx stores
    __syncthreads();
    const int t0 = m0 >> 6;
    for (int s = 0; s < 4; s++) {
        if (warp_n == s) {
#pragma unroll
            for (int mi = 0; mi < 4; mi++)
#pragma unroll
                for (int ni = 0; ni < 4; ni++) {
                    int row = warp_m * 64 + mi * 16 + (lane >> 2);
                    int col = ni * 8 + (lane & 3) * 2;
                    Cs[row * CSTRIDE + col]           = acc[mi][ni][0];
                    Cs[row * CSTRIDE + col + 1]       = acc[mi][ni][1];
                    Cs[(row + 8) * CSTRIDE + col]     = acc[mi][ni][2];
                    Cs[(row + 8) * CSTRIDE + col + 1] = acc[mi][ni][3];
                }
        }
        __syncthreads();
        for (int i = tid; i < 1024; i += 256) {
            int jl   = i >> 5;         // 0..31
            int rest = i & 31;
            int tl   = rest >> 4;      // 0..1
            int q    = rest & 15;      // float4 within b
            int jg   = n0 + s * 32 + jl;
            float bias = b_ih[jg] + b_hh[jg];
            int rb = tl * 64 + q * 4;
            float4 v;
            v.x = Cs[(rb + 0) * CSTRIDE + jl] + bias;
            v.y = Cs[(rb + 1) * CSTRIDE + jl] + bias;
            v.z = Cs[(rb + 2) * CSTRIDE + jl] + bias;
            v.w = Cs[(rb + 3) * CSTRIDE + jl] + bias;
            *(float4*)(g_gx + ((size_t)(t0 + tl) * FOURH + jg) * BB + q * 4) = v;
        }
        __syncthreads();
    }
}

// ---------------- Phase 2: persistent sequential LSTM (unchanged, verified) -----
#define HS_STRIDE 132
#define HSBUF (64 * HS_STRIDE)
#define GS_STRIDE 65
#define SMEM_P2 ((32 * HH + 2 * HSBUF + 32 * GS_STRIDE) * 4)

__device__ __forceinline__ float sigmoidf_(float x) {
    return 1.0f / (1.0f + __expf(-x));
}

__global__ __launch_bounds__(NTHR, 1)
void lstm_seq_kernel(const float* __restrict__ h0,
                     const float* __restrict__ c0,
                     const float* __restrict__ Whh,
                     float* __restrict__ out) {
    extern __shared__ float sm[];
    float* Wsh = sm;
    float* hsA = sm + 32 * HH;
    float* hsB = hsA + HSBUF;
    float* gsh = hsB + HSBUF;

    const int tid  = threadIdx.x;
    const int ct   = blockIdx.x;
    const int lane = tid & 31;
    const int w    = tid >> 5;
    const int jg   = w & 3;
    const int bh   = w >> 2;
    const int b    = bh * 32 + lane;

    {
        const float4* Wv = (const float4*)Whh;
        float4* Ws4 = (float4*)Wsh;
        for (int idx = tid; idx < 32 * 256; idx += NTHR) {
            int row  = idx >> 8;
            int col  = idx & 255;
            int gate = row >> 3, nl = row & 7;
            size_t jgl = (size_t)gate * 1024 + ct * 8 + nl;
            Ws4[row * 256 + col] = Wv[jgl * 256 + col];
        }
    }

    const int be  = tid >> 2;
    const int nl0 = (tid & 3) * 2;
    float c_reg[2];
    c_reg[0] = c0[be * HH + ct * 8 + nl0];
    c_reg[1] = c0[be * HH + ct * 8 + nl0 + 1];
    __syncthreads();

    const float4* wbase = (const float4*)Wsh + (jg * 8) * 256;

    for (int t = 0; t < TT; t++) {
        const float* hsrc = (t == 0) ? h0 : g_h[t & 1];

        float4 v[8];
#pragma unroll
        for (int i = 0; i < 8; i++)
            v[i] = __ldcg((const float4*)(hsrc + (size_t)(w + 8 * i) * HH) + lane);
#pragma unroll
        for (int i = 0; i < 8; i++)
            *(float4*)(hsA + (w + 8 * i) * HS_STRIDE + 4 * lane) = v[i];
        __syncthreads();

        float acc[8];
#pragma unroll
        for (int jj = 0; jj < 8; jj++) acc[jj] = 0.f;

        for (int c = 0; c < 8; c++) {
            if (c < 7) {
                int kc = (c + 1) * 128;
#pragma unroll
                for (int i = 0; i < 8; i++)
                    v[i] = __ldcg((const float4*)(hsrc + (size_t)(w + 8 * i) * HH + kc) + lane);
            }

            const float* cur = (c & 1) ? hsB : hsA;
            const float*  hp = cur + b * HS_STRIDE;
            const float4* wb = wbase + ((c * 128) >> 2);
#pragma unroll 4
            for (int k4 = 0; k4 < 32; k4++) {
                float4 hv = *(const float4*)(hp + 4 * k4);
#pragma unroll
                for (int jj = 0; jj < 8; jj++) {
                    float4 wv = wb[jj * 256 + k4];
                    acc[jj] = fmaf(wv.x, hv.x, acc[jj]);
                    acc[jj] = fmaf(wv.y, hv.y, acc[jj]);
                    acc[jj] = fmaf(wv.z, hv.z, acc[jj]);
                    acc[jj] = fmaf(wv.w, hv.w, acc[jj]);
                }
            }

            if (c < 7) {
                __syncthreads();
                float* nxt = (c & 1) ? hsA : hsB;
#pragma unroll
                for (int i = 0; i < 8; i++)
                    *(float4*)(nxt + (w + 8 * i) * HS_STRIDE + 4 * lane) = v[i];
                __syncthreads();
            }
        }

        {
            const float* gp = g_gx + ((size_t)t * FOURH + jg * 1024 + ct * 8) * BB + b;
#pragma unroll
            for (int jj = 0; jj < 8; jj++)
                acc[jj] += __ldcs(gp + jj * BB);
        }

        __syncthreads();
#pragma unroll
        for (int jj = 0; jj < 8; jj++)
            gsh[(jg * 8 + jj) * GS_STRIDE + b] = acc[jj];
        __syncthreads();

        float* hdst = g_h[(t + 1) & 1];
        float hv2[2], cv2[2];
#pragma unroll
        for (int r = 0; r < 2; r++) {
            int nl = nl0 + r;
            float ig = gsh[(0  + nl) * GS_STRIDE + be];
            float fg = gsh[(8  + nl) * GS_STRIDE + be];
            float gg = gsh[(16 + nl) * GS_STRIDE + be];
            float og = gsh[(24 + nl) * GS_STRIDE + be];
            float iv = sigmoidf_(ig);
            float fv = sigmoidf_(fg);
            float gv = tanhf(gg);
            float ov = sigmoidf_(og);
            float cv = fv * c_reg[r] + iv * gv;
            float hv = ov * tanhf(cv);
            c_reg[r] = cv;
            hv2[r] = hv; cv2[r] = cv;
        }
        {
            size_t off = (size_t)be * HH + ct * 8 + nl0;
            float2 hvv = make_float2(hv2[0], hv2[1]);
            *(float2*)(out + (size_t)t * BH + off) = hvv;
            __stcg((float2*)(hdst + off), hvv);
            if (t == TT - 1) {
                *(float2*)(out + (size_t)TBH + off)      = hvv;
                *(float2*)(out + (size_t)TBH + BH + off) = make_float2(cv2[0], cv2[1]);
            }
        }

        __threadfence();
        __syncthreads();
        if (tid == 0) {
            atomicAdd(&g_bar[t], 1u);
            while (*((volatile unsigned int*)&g_bar[t]) < (unsigned)NCTA) { }
            __threadfence();
        }
        __syncthreads();
    }
}

// ---------------- launch --------------------------------------------------------
extern "C" void kernel_launch(void* const* d_in, const int* in_sizes, int n_in,
                              void* d_out, int out_size) {
    const float* X    = (const float*)d_in[0];
    const float* h0   = (const float*)d_in[1];
    const float* c0   = (const float*)d_in[2];
    const float* Wih  = (const float*)d_in[3];
    const float* Whh  = (const float*)d_in[4];
    const float* b_ih = (const float*)d_in[5];
    const float* b_hh = (const float*)d_in[6];
    float* out = (float*)d_out;

    cudaFuncSetAttribute(gemm_xwih_mma,
                         cudaFuncAttributeMaxDynamicSharedMemorySize, SMEM_G);
    cudaFuncSetAttribute(lstm_seq_kernel,
                         cudaFuncAttributeMaxDynamicSharedMemorySize, SMEM_P2);

    convert_split_kernel<<<1024, 256>>>(X, Wih);

    dim3 g1(FOURH / 128, (TT * BB) / 128);   // (32, 256)
    gemm_xwih_mma<<<g1, 256, SMEM_G>>>(b_ih, b_hh);

    lstm_seq_kernel<<<NCTA, NTHR, SMEM_P2>>>(h0, c0, Whh, out);
}

// round 17
// speedup vs baseline: 2.3434x; 2.0178x over previous
#include <cuda_runtime.h>
#include <cuda_bf16.h>
#include <cstdint>
#include <cstddef>

// Problem dims
#define TT 512
#define BB 64
#define DD 1024
#define HH 1024
#define FOURH 4096
#define TBH (TT * BB * HH)
#define BH  (BB * HH)

#define NCTA 128
#define NTHR 256

// ---------------- scratch ------------------------------------------------------
__device__ float g_gx[(size_t)TT * FOURH * BB];        // 512 MB: Gx[t][j][b]
__device__ __nv_bfloat16 g_hhi[2][BH];                 // h hi, double buffered
__device__ __nv_bfloat16 g_hlo[2][BH];                 // h lo
__device__ unsigned int g_bar[TT];
__device__ __nv_bfloat16 g_xhi[(size_t)TT * BB * DD];
__device__ __nv_bfloat16 g_xlo[(size_t)TT * BB * DD];
__device__ __nv_bfloat16 g_whi[(size_t)FOURH * DD];
__device__ __nv_bfloat16 g_wlo[(size_t)FOURH * DD];

// ---------------- Phase 0: split fp32 -> bf16 hi/lo; zero barriers --------------
#define NX4 ((size_t)TT * BB * DD / 4)
#define NW4 ((size_t)FOURH * DD / 4)
#define NH4 ((size_t)BH / 4)

__device__ __forceinline__ void split4(float4 v, __nv_bfloat162* hp, __nv_bfloat162* lp) {
    __nv_bfloat16 hx = __float2bfloat16_rn(v.x);
    __nv_bfloat16 hy = __float2bfloat16_rn(v.y);
    __nv_bfloat16 hz = __float2bfloat16_rn(v.z);
    __nv_bfloat16 hw = __float2bfloat16_rn(v.w);
    __nv_bfloat16 lx = __float2bfloat16_rn(v.x - __bfloat162float(hx));
    __nv_bfloat16 ly = __float2bfloat16_rn(v.y - __bfloat162float(hy));
    __nv_bfloat16 lz = __float2bfloat16_rn(v.z - __bfloat162float(hz));
    __nv_bfloat16 lw = __float2bfloat16_rn(v.w - __bfloat162float(hw));
    hp[0] = __halves2bfloat162(hx, hy);
    hp[1] = __halves2bfloat162(hz, hw);
    lp[0] = __halves2bfloat162(lx, ly);
    lp[1] = __halves2bfloat162(lz, lw);
}

__global__ __launch_bounds__(256)
void convert_split_kernel(const float* __restrict__ X, const float* __restrict__ W,
                          const float* __restrict__ h0) {
    if (blockIdx.x == 0) {
        for (int i = threadIdx.x; i < TT; i += blockDim.x) g_bar[i] = 0u;
    }
    size_t stride = (size_t)gridDim.x * blockDim.x;
    size_t total = NX4 + NW4 + NH4;
    for (size_t i = (size_t)blockIdx.x * blockDim.x + threadIdx.x; i < total; i += stride) {
        if (i < NX4) {
            float4 v = ((const float4*)X)[i];
            split4(v, (__nv_bfloat162*)g_xhi + i * 2, (__nv_bfloat162*)g_xlo + i * 2);
        } else if (i < NX4 + NW4) {
            size_t j = i - NX4;
            float4 v = ((const float4*)W)[j];
            split4(v, (__nv_bfloat162*)g_whi + j * 2, (__nv_bfloat162*)g_wlo + j * 2);
        } else {
            size_t j = i - NX4 - NW4;
            float4 v = ((const float4*)h0)[j];
            split4(v, (__nv_bfloat162*)g_hhi[0] + j * 2, (__nv_bfloat162*)g_hlo[0] + j * 2);
        }
    }
}

// ---------------- shared mma helpers --------------------------------------------
__device__ __forceinline__ uint32_t smem_u32(const void* p) {
    return (uint32_t)__cvta_generic_to_shared(p);
}
__device__ __forceinline__ void ldsm4(uint32_t* r, uint32_t addr) {
    asm volatile("ldmatrix.sync.aligned.m8n8.x4.shared.b16 {%0,%1,%2,%3}, [%4];\n"
                 : "=r"(r[0]), "=r"(r[1]), "=r"(r[2]), "=r"(r[3]) : "r"(addr));
}
__device__ __forceinline__ void mma16816(float* c, const uint32_t* a, uint32_t b0, uint32_t b1) {
    asm volatile(
        "mma.sync.aligned.m16n8k16.row.col.f32.bf16.bf16.f32 "
        "{%0,%1,%2,%3}, {%4,%5,%6,%7}, {%8,%9}, {%0,%1,%2,%3};\n"
        : "+f"(c[0]), "+f"(c[1]), "+f"(c[2]), "+f"(c[3])
        : "r"(a[0]), "r"(a[1]), "r"(a[2]), "r"(a[3]), "r"(b0), "r"(b1));
}

// ---------------- Phase 1: bf16-split tensor-core GEMM (2 CTAs/SM) --------------
#define ASTRIDE 40
#define ABYTES (128 * ASTRIDE * 2)
#define CSTRIDE 33
#define SMEM_G (2 * ABYTES * 2 + 128 * CSTRIDE * 4)

__global__ __launch_bounds__(256, 2)
void gemm_xwih_mma(const float* __restrict__ b_ih, const float* __restrict__ b_hh) {
    extern __shared__ char smg[];
    __nv_bfloat16* As = (__nv_bfloat16*)smg;
    __nv_bfloat16* Bs = (__nv_bfloat16*)(smg + 2 * ABYTES);
    float*         Cs = (float*)(smg + 4 * ABYTES);

    const int tid  = threadIdx.x;
    const int lane = tid & 31;
    const int wid  = tid >> 5;
    const int warp_m = wid >> 2;
    const int warp_n = wid & 3;
    const int m0 = blockIdx.y * 128;
    const int n0 = blockIdx.x * 128;

    const int lr = tid >> 2;
    const int lk = (tid & 3) * 8;

    const __nv_bfloat16* Aseg[3] = {g_xhi, g_xhi, g_xlo};
    const __nv_bfloat16* Bseg[3] = {g_whi, g_wlo, g_whi};

    float acc[4][4][4];
#pragma unroll
    for (int mi = 0; mi < 4; mi++)
#pragma unroll
        for (int ni = 0; ni < 4; ni++)
#pragma unroll
            for (int r = 0; r < 4; r++) acc[mi][ni][r] = 0.f;

    float4 pa[2], pb[2];
    {
        const __nv_bfloat16* Ap = Aseg[0] + (size_t)(m0 + lr) * DD + lk;
        const __nv_bfloat16* Bp = Bseg[0] + (size_t)(n0 + lr) * DD + lk;
        pa[0] = *(const float4*)Ap;  pa[1] = *(const float4*)(Ap + (size_t)64 * DD);
        pb[0] = *(const float4*)Bp;  pb[1] = *(const float4*)(Bp + (size_t)64 * DD);
    }
#pragma unroll
    for (int r = 0; r < 2; r++) {
        *(float4*)(As + (lr + 64 * r) * ASTRIDE + lk) = pa[r];
        *(float4*)(Bs + (lr + 64 * r) * ASTRIDE + lk) = pb[r];
    }
    __syncthreads();

    const int NIT = 96;
    for (int it = 0; it < NIT; it++) {
        const int buf = it & 1;
        __nv_bfloat16* Ab = As + buf * (128 * ASTRIDE);
        __nv_bfloat16* Bb = Bs + buf * (128 * ASTRIDE);

        if (it < NIT - 1) {
            int nit = it + 1;
            int seg = nit >> 5;
            int kc  = (nit & 31) * 32;
            const __nv_bfloat16* Ap = Aseg[seg] + (size_t)(m0 + lr) * DD + kc + lk;
            const __nv_bfloat16* Bp = Bseg[seg] + (size_t)(n0 + lr) * DD + kc + lk;
            pa[0] = *(const float4*)Ap;  pa[1] = *(const float4*)(Ap + (size_t)64 * DD);
            pb[0] = *(const float4*)Bp;  pb[1] = *(const float4*)(Bp + (size_t)64 * DD);
        }

#pragma unroll
        for (int kk = 0; kk < 32; kk += 16) {
            uint32_t af[4][4];
#pragma unroll
            for (int mi = 0; mi < 4; mi++)
                ldsm4(af[mi], smem_u32(Ab + (warp_m * 64 + mi * 16 + (lane & 15)) * ASTRIDE
                                          + kk + (lane >> 4) * 8));
            uint32_t bf[2][4];
#pragma unroll
            for (int bi = 0; bi < 2; bi++)
                ldsm4(bf[bi], smem_u32(Bb + (warp_n * 32 + bi * 16 + (lane & 15)) * ASTRIDE
                                          + kk + (lane >> 4) * 8));
#pragma unroll
            for (int mi = 0; mi < 4; mi++)
#pragma unroll
                for (int ni = 0; ni < 4; ni++) {
                    int bi = ni >> 1, sub = ni & 1;
                    mma16816(acc[mi][ni], af[mi], bf[bi][sub], bf[bi][sub + 2]);
                }
        }

        if (it < NIT - 1) {
            __nv_bfloat16* An = As + (buf ^ 1) * (128 * ASTRIDE);
            __nv_bfloat16* Bn = Bs + (buf ^ 1) * (128 * ASTRIDE);
#pragma unroll
            for (int r = 0; r < 2; r++) {
                *(float4*)(An + (lr + 64 * r) * ASTRIDE + lk) = pa[r];
                *(float4*)(Bn + (lr + 64 * r) * ASTRIDE + lk) = pb[r];
            }
            __syncthreads();
        }
    }

    __syncthreads();
    const int t0 = m0 >> 6;
    for (int s = 0; s < 4; s++) {
        if (warp_n == s) {
#pragma unroll
            for (int mi = 0; mi < 4; mi++)
#pragma unroll
                for (int ni = 0; ni < 4; ni++) {
                    int row = warp_m * 64 + mi * 16 + (lane >> 2);
                    int col = ni * 8 + (lane & 3) * 2;
                    Cs[row * CSTRIDE + col]           = acc[mi][ni][0];
                    Cs[row * CSTRIDE + col + 1]       = acc[mi][ni][1];
                    Cs[(row + 8) * CSTRIDE + col]     = acc[mi][ni][2];
                    Cs[(row + 8) * CSTRIDE + col + 1] = acc[mi][ni][3];
                }
        }
        __syncthreads();
        for (int i = tid; i < 1024; i += 256) {
            int jl   = i >> 5;
            int rest = i & 31;
            int tl   = rest >> 4;
            int q    = rest & 15;
            int jg   = n0 + s * 32 + jl;
            float bias = b_ih[jg] + b_hh[jg];
            int rb = tl * 64 + q * 4;
            float4 v;
            v.x = Cs[(rb + 0) * CSTRIDE + jl] + bias;
            v.y = Cs[(rb + 1) * CSTRIDE + jl] + bias;
            v.z = Cs[(rb + 2) * CSTRIDE + jl] + bias;
            v.w = Cs[(rb + 3) * CSTRIDE + jl] + bias;
            *(float4*)(g_gx + ((size_t)(t0 + tl) * FOURH + jg) * BB + q * 4) = v;
        }
        __syncthreads();
    }
}

// ---------------- Phase 2: persistent sequential LSTM, tensor-core recurrence ---
// CTA ct owns 32 gate-rows of W_hh (bf16 hi/lo in smem, ldmatrix layout).
// Per step: C[64b x 32j] = Ahi*Bhi + Ahi*Blo + Alo*Bhi via mma.sync, fp32 accum.
// Warps: 4(m16) x 2(n16). h streamed in 8 k-chunks of 128, double buffered.
#define KC 128
#define HSTR 136          // bf16 stride, 272 B rows, conflict-free ldsm
#define WSTR 1032         // bf16 stride, 2064 B rows, conflict-free ldsm
#define OFF_WHI 0
#define OFF_WLO (32 * WSTR * 2)                      // 66048
#define OFF_H   (2 * 32 * WSTR * 2)                  // 132096
#define HBUF_B  (2 * 64 * HSTR * 2)                  // 34816 per buffer (hi+lo)
#define OFF_GSH (OFF_H + 2 * HBUF_B)                 // 201728
#define GS_STRIDE 65
#define SMEM_P2 (OFF_GSH + 32 * GS_STRIDE * 4)       // 210048 bytes

__device__ __forceinline__ float sigmoidf_(float x) {
    return 1.0f / (1.0f + __expf(-x));
}

__global__ __launch_bounds__(NTHR, 1)
void lstm_seq_kernel(const float* __restrict__ c0,
                     const float* __restrict__ Whh,
                     float* __restrict__ out) {
    extern __shared__ char smp[];
    __nv_bfloat16* Whi_s = (__nv_bfloat16*)(smp + OFF_WHI);
    __nv_bfloat16* Wlo_s = (__nv_bfloat16*)(smp + OFF_WLO);
    float* gsh = (float*)(smp + OFF_GSH);

    const int tid  = threadIdx.x;
    const int ct   = blockIdx.x;
    const int lane = tid & 31;
    const int w    = tid >> 5;
    const int warp_m = w >> 1;     // 0..3 : batch rows warp_m*16..+15
    const int warp_n = w & 1;      // 0..1 : j rows warp_n*16..+15

    // ---- load + split W_hh slice into smem (once) ----
    {
        const float4* Wv = (const float4*)Whh;
        for (int idx = tid; idx < 32 * 256; idx += NTHR) {
            int row = idx >> 8;          // local j 0..31
            int col = idx & 255;         // float4 unit
            int gate = row >> 3, nl = row & 7;
            size_t jgl = (size_t)gate * 1024 + ct * 8 + nl;
            float4 v = Wv[jgl * 256 + col];
            split4(v, (__nv_bfloat162*)(Whi_s + row * WSTR + col * 4),
                      (__nv_bfloat162*)(Wlo_s + row * WSTR + col * 4));
        }
    }

    // ---- cell state: thread owns (be = tid>>2, nl0 = (tid&3)*2 + {0,1}) ----
    const int be  = tid >> 2;
    const int nl0 = (tid & 3) * 2;
    float c_reg[2];
    c_reg[0] = c0[be * HH + ct * 8 + nl0];
    c_reg[1] = c0[be * HH + ct * 8 + nl0 + 1];
    __syncthreads();

    // loader mapping: idx = tid + i*256 -> row = idx>>4 (0..63), q = idx&15
    const int lrow = tid >> 4;
    const int lq   = tid & 15;

    for (int t = 0; t < TT; t++) {
        const __nv_bfloat16* shi = g_hhi[t & 1];
        const __nv_bfloat16* slo = g_hlo[t & 1];

        float4 vh[4], vl[4];
        // prologue: chunk 0 -> buffer 0
#pragma unroll
        for (int i = 0; i < 4; i++) {
            int row = lrow + i * 16;
            vh[i] = __ldcg((const float4*)(shi + (size_t)row * HH) + lq);
            vl[i] = __ldcg((const float4*)(slo + (size_t)row * HH) + lq);
        }
        {
            __nv_bfloat16* Ahi = (__nv_bfloat16*)(smp + OFF_H);
            __nv_bfloat16* Alo = Ahi + 64 * HSTR;
#pragma unroll
            for (int i = 0; i < 4; i++) {
                int row = lrow + i * 16;
                *(float4*)(Ahi + row * HSTR + lq * 8) = vh[i];
                *(float4*)(Alo + row * HSTR + lq * 8) = vl[i];
            }
        }
        __syncthreads();

        float acc[2][4];
#pragma unroll
        for (int ni = 0; ni < 2; ni++)
#pragma unroll
            for (int r = 0; r < 4; r++) acc[ni][r] = 0.f;

        for (int c = 0; c < 8; c++) {
            if (c < 7) {
                int kc = (c + 1) * KC;
#pragma unroll
                for (int i = 0; i < 4; i++) {
                    int row = lrow + i * 16;
                    vh[i] = __ldcg((const float4*)(shi + (size_t)row * HH + kc) + lq);
                    vl[i] = __ldcg((const float4*)(slo + (size_t)row * HH + kc) + lq);
                }
            }

            __nv_bfloat16* Ahi = (__nv_bfloat16*)(smp + OFF_H + (c & 1) * HBUF_B);
            __nv_bfloat16* Alo = Ahi + 64 * HSTR;
            const int kbase = c * KC;

#pragma unroll
            for (int k16 = 0; k16 < 8; k16++) {
                int kk = k16 * 16;
                uint32_t ahi[4], alo[4], bhi[4], blo[4];
                ldsm4(ahi, smem_u32(Ahi + (warp_m * 16 + (lane & 15)) * HSTR
                                        + kk + (lane >> 4) * 8));
                ldsm4(alo, smem_u32(Alo + (warp_m * 16 + (lane & 15)) * HSTR
                                        + kk + (lane >> 4) * 8));
                ldsm4(bhi, smem_u32(Whi_s + (warp_n * 16 + (lane & 15)) * WSTR
                                        + kbase + kk + (lane >> 4) * 8));
                ldsm4(blo, smem_u32(Wlo_s + (warp_n * 16 + (lane & 15)) * WSTR
                                        + kbase + kk + (lane >> 4) * 8));
#pragma unroll
                for (int ni = 0; ni < 2; ni++) {
                    mma16816(acc[ni], ahi, bhi[ni], bhi[ni + 2]);
                    mma16816(acc[ni], ahi, blo[ni], blo[ni + 2]);
                    mma16816(acc[ni], alo, bhi[ni], bhi[ni + 2]);
                }
            }

            if (c < 7) {
                __syncthreads();
                __nv_bfloat16* Nhi = (__nv_bfloat16*)(smp + OFF_H + ((c + 1) & 1) * HBUF_B);
                __nv_bfloat16* Nlo = Nhi + 64 * HSTR;
#pragma unroll
                for (int i = 0; i < 4; i++) {
                    int row = lrow + i * 16;
                    *(float4*)(Nhi + row * HSTR + lq * 8) = vh[i];
                    *(float4*)(Nlo + row * HSTR + lq * 8) = vl[i];
                }
                __syncthreads();
            }
        }

        // epilogue: add Gx, write gates to gsh
        {
            const float* gxt = g_gx + (size_t)t * FOURH * BB;
#pragma unroll
            for (int ni = 0; ni < 2; ni++)
#pragma unroll
                for (int r = 0; r < 4; r++) {
                    int jl = warp_n * 16 + ni * 8 + (lane & 3) * 2 + (r & 1);
                    int b  = warp_m * 16 + (lane >> 2) + ((r >> 1) * 8);
                    int gate = jl >> 3, nl = jl & 7;
                    int jglob = gate * 1024 + ct * 8 + nl;
                    gsh[jl * GS_STRIDE + b] =
                        acc[ni][r] + __ldcs(gxt + (size_t)jglob * BB + b);
                }
        }
        __syncthreads();

        // elementwise cell update
        float hv2[2], cv2[2];
#pragma unroll
        for (int r = 0; r < 2; r++) {
            int nl = nl0 + r;
            float ig = gsh[(0  + nl) * GS_STRIDE + be];
            float fg = gsh[(8  + nl) * GS_STRIDE + be];
            float gg = gsh[(16 + nl) * GS_STRIDE + be];
            float og = gsh[(24 + nl) * GS_STRIDE + be];
            float iv = sigmoidf_(ig);
            float fv = sigmoidf_(fg);
            float gv = tanhf(gg);
            float ov = sigmoidf_(og);
            float cv = fv * c_reg[r] + iv * gv;
            float hv = ov * tanhf(cv);
            c_reg[r] = cv;
            hv2[r] = hv; cv2[r] = cv;
        }
        {
            size_t off = (size_t)be * HH + ct * 8 + nl0;
            *(float2*)(out + (size_t)t * BH + off) = make_float2(hv2[0], hv2[1]);
            int nb = (t + 1) & 1;
            __nv_bfloat16 h0b = __float2bfloat16_rn(hv2[0]);
            __nv_bfloat16 h1b = __float2bfloat16_rn(hv2[1]);
            __nv_bfloat16 l0b = __float2bfloat16_rn(hv2[0] - __bfloat162float(h0b));
            __nv_bfloat16 l1b = __float2bfloat16_rn(hv2[1] - __bfloat162float(h1b));
            *(__nv_bfloat162*)(g_hhi[nb] + off) = __halves2bfloat162(h0b, h1b);
            *(__nv_bfloat162*)(g_hlo[nb] + off) = __halves2bfloat162(l0b, l1b);
            if (t == TT - 1) {
                *(float2*)(out + (size_t)TBH + off)      = make_float2(hv2[0], hv2[1]);
                *(float2*)(out + (size_t)TBH + BH + off) = make_float2(cv2[0], cv2[1]);
            }
        }

        // ---- grid barrier ----
        __threadfence();
        __syncthreads();
        if (tid == 0) {
            atomicAdd(&g_bar[t], 1u);
            while (*((volatile unsigned int*)&g_bar[t]) < (unsigned)NCTA) { }
            __threadfence();
        }
        __syncthreads();
    }
}

// ---------------- launch --------------------------------------------------------
extern "C" void kernel_launch(void* const* d_in, const int* in_sizes, int n_in,
                              void* d_out, int out_size) {
    const float* X    = (const float*)d_in[0];
    const float* h0   = (const float*)d_in[1];
    const float* c0   = (const float*)d_in[2];
    const float* Wih  = (const float*)d_in[3];
    const float* Whh  = (const float*)d_in[4];
    const float* b_ih = (const float*)d_in[5];
    const float* b_hh = (const float*)d_in[6];
    float* out = (float*)d_out;

    cudaFuncSetAttribute(gemm_xwih_mma,
                         cudaFuncAttributeMaxDynamicSharedMemorySize, SMEM_G);
    cudaFuncSetAttribute(lstm_seq_kernel,
                         cudaFuncAttributeMaxDynamicSharedMemorySize, SMEM_P2);

    convert_split_kernel<<<1024, 256>>>(X, Wih, h0);

    dim3 g1(FOURH / 128, (TT * BB) / 128);
    gemm_xwih_mma<<<g1, 256, SMEM_G>>>(b_ih, b_hh);

    lstm_seq_kernel<<<NCTA, NTHR, SMEM_P2>>>(c0, Whh, out);
}